// round 5
// baseline (speedup 1.0000x reference)
#include <cuda_runtime.h>
#include <math.h>

#define NCLS 19
#define BB   8
#define CC   512
#define HW   16384      // 128*128
#define GPB  8          // channels per block
#define THREADS_A 512   // 16 warps: tensor = w&1, local channel = w>>1

// Scratch (single-writer per slot -> deterministic, no float atomics)
__device__ float g_partial[2][BB][NCLS][CC];   // [tensor][b][class][channel]
__device__ int   g_cnt_part[BB][NCLS];
__device__ float g_norm[2][NCLS][CC];          // normalized class means

// ---------------------------------------------------------------------------
// Kernel A: streaming segment-sum.
// Block (cg, b): channels [cg*8, cg*8+8) of image b, both tensors.
// Warp w: tensor = w&1, local channel = w>>1. Private accumulator slab
// acc[w][19][32]: bank == lane -> conflict-free, no cross-thread sharing.
// smem/block = 16*2432 + 16384 + 128 = 55424 B -> 4 blocks/SM = 64 warps.
// ---------------------------------------------------------------------------
__global__ void __launch_bounds__(THREADS_A, 4) kA(const float* __restrict__ fs,
                                                   const float* __restrict__ ft,
                                                   const int*   __restrict__ lab) {
    extern __shared__ unsigned char smem[];
    float*         acc   = (float*)smem;                      // 16*19*32 floats
    unsigned char* labu8 = smem + 16 * NCLS * 32 * 4;         // 16384 B
    int*           cnt   = (int*)(labu8 + HW);                // 32 ints

    const int tid  = threadIdx.x;
    const int lane = tid & 31;
    const int w    = tid >> 5;
    const int cg   = blockIdx.x;
    const int b    = blockIdx.y;

    // zero accumulators
    for (int i = tid; i < 16 * NCLS * 32; i += THREADS_A) acc[i] = 0.0f;
    if (tid < 32) cnt[tid] = 0;

    // labels -> shared u8 (values 0..18 fit in a byte)
    const int4* lab4 = (const int4*)(lab + (size_t)b * HW);
    uchar4*     lu4  = (uchar4*)labu8;
    for (int i = tid; i < HW / 4; i += THREADS_A) {
        int4 v = __ldg(lab4 + i);
        lu4[i] = make_uchar4((unsigned char)v.x, (unsigned char)v.y,
                             (unsigned char)v.z, (unsigned char)v.w);
    }
    __syncthreads();

    const int tensor = w & 1;
    const int cl     = w >> 1;                 // 0..7
    const int c      = cg * GPB + cl;
    const float4* f  = (const float4*)((tensor ? ft : fs) + ((size_t)b * CC + c) * HW);
    float* accw      = acc + w * NCLS * 32;
    const unsigned int* labw = (const unsigned int*)labu8;  // 4 packed labels / word

    #pragma unroll 4
    for (int i = lane; i < HW / 4; i += 32) {
        unsigned int l = labw[i];
        float4 v = __ldcs(f + i);              // streaming: no reuse, evict-first
        accw[((l      ) & 0xFFu) * 32 + lane] += v.x;
        accw[((l >>  8) & 0xFFu) * 32 + lane] += v.y;
        accw[((l >> 16) & 0xFFu) * 32 + lane] += v.z;
        accw[((l >> 24)        ) * 32 + lane] += v.w;
    }

    // per-class pixel counts: only one block per image
    if (cg == 0) {
        for (int i = tid; i < HW; i += THREADS_A)
            atomicAdd(&cnt[labu8[i]], 1);      // shared int atomics: deterministic
    }
    __syncthreads();

    // flush: each warp reduces its own [19][32] slab
    for (int k = 0; k < NCLS; k++) {
        float v = accw[k * 32 + lane];
        #pragma unroll
        for (int o = 16; o; o >>= 1) v += __shfl_down_sync(0xFFFFFFFFu, v, o);
        if (lane == 0) g_partial[tensor][b][k][c] = v;
    }
    if (cg == 0 && tid < NCLS) g_cnt_part[b][tid] = cnt[tid];
}

// ---------------------------------------------------------------------------
// Kernel C1: mean + L2-normalize. Grid 38: block = (tensor s, class k).
// 128 threads; thread t owns channels {t, t+128, t+256, t+384}. Register
// means, warp reduce + tiny smem cross-warp combine. Spreads the 622 KB of
// g_partial reads over 38 SMs.
// ---------------------------------------------------------------------------
__global__ void __launch_bounds__(128) kC1() {
    __shared__ float wss[4];
    __shared__ float sh_denom;
    const int t    = threadIdx.x;
    const int lane = t & 31;
    const int w    = t >> 5;
    const int task = blockIdx.x;
    const int s    = task >= NCLS ? 1 : 0;
    const int k    = task >= NCLS ? task - NCLS : task;

    if (t == 0) {
        int c = 0;
        #pragma unroll
        for (int b = 0; b < BB; b++) c += g_cnt_part[b][k];
        sh_denom = fmaxf((float)c, 1.0f);
    }
    __syncthreads();
    const float denom = sh_denom;

    float m[4];
    float ss = 0.0f;
    #pragma unroll
    for (int ch = 0; ch < 4; ch++) {
        const int c = ch * 128 + t;
        float sum = 0.0f;
        #pragma unroll
        for (int b = 0; b < BB; b++) sum += g_partial[s][b][k][c];
        float mean = sum / denom;
        m[ch] = mean;
        ss += mean * mean;
    }
    #pragma unroll
    for (int o = 16; o; o >>= 1) ss += __shfl_xor_sync(0xFFFFFFFFu, ss, o);
    if (lane == 0) wss[w] = ss;
    __syncthreads();
    const float tot = wss[0] + wss[1] + wss[2] + wss[3];
    const float inv = 1.0f / fmaxf(sqrtf(tot), 1e-12f);
    #pragma unroll
    for (int ch = 0; ch < 4; ch++)
        g_norm[s][k][ch * 128 + t] = m[ch] * inv;
}

// ---------------------------------------------------------------------------
// Kernel C2: logits (19x19 warp-dots), logsumexp, masked mean -> scalar.
// ---------------------------------------------------------------------------
__global__ void __launch_bounds__(640) kC2(float* __restrict__ out) {
    __shared__ float sh_log[NCLS][NCLS];
    __shared__ int   sh_cnt[NCLS];
    __shared__ float sh_pc[NCLS];
    const int tid  = threadIdx.x;
    const int w    = tid >> 5;
    const int lane = tid & 31;

    if (tid < NCLS) {
        int c = 0;
        #pragma unroll
        for (int b = 0; b < BB; b++) c += g_cnt_part[b][tid];
        sh_cnt[tid] = c;
    }

    if (w < NCLS) {                       // warp w -> logits row w
        const float* si = &g_norm[0][w][0];
        for (int j = 0; j < NCLS; j++) {
            const float* tj = &g_norm[1][j][0];
            float p = 0.0f;
            #pragma unroll
            for (int ch = 0; ch < CC / 32; ch++)
                p += si[ch * 32 + lane] * tj[ch * 32 + lane];
            #pragma unroll
            for (int o = 16; o; o >>= 1) p += __shfl_down_sync(0xFFFFFFFFu, p, o);
            if (lane == 0) sh_log[w][j] = p * 10.0f;   // / TEMP (0.1)
        }
    }
    __syncthreads();

    if (tid < NCLS) {
        float mx = -1e30f;
        for (int j = 0; j < NCLS; j++) mx = fmaxf(mx, sh_log[tid][j]);
        float s = 0.0f;
        for (int j = 0; j < NCLS; j++) s += expf(sh_log[tid][j] - mx);
        float lse = mx + logf(s);
        sh_pc[tid] = sh_log[tid][tid] - lse;
    }
    __syncthreads();

    if (tid == 0) {
        float sum = 0.0f;
        int np = 0;
        for (int k = 0; k < NCLS; k++)
            if (sh_cnt[k] > 0) { sum += sh_pc[k]; np++; }
        out[0] = -sum / (float)np;
    }
}

// ---------------------------------------------------------------------------
extern "C" void kernel_launch(void* const* d_in, const int* in_sizes, int n_in,
                              void* d_out, int out_size) {
    const float* fs  = (const float*)d_in[0];
    const float* ft  = (const float*)d_in[1];
    const int*   lab = (const int*)d_in[2];

    const size_t smemA = (size_t)16 * NCLS * 32 * 4 + HW + 32 * 4;  // 55424 B
    cudaFuncSetAttribute(kA, cudaFuncAttributeMaxDynamicSharedMemorySize, (int)smemA);

    kA<<<dim3(CC / GPB, BB), THREADS_A, smemA>>>(fs, ft, lab);
    kC1<<<2 * NCLS, 128>>>();
    kC2<<<1, 640>>>((float*)d_out);
}

// round 6
// speedup vs baseline: 1.1265x; 1.1265x over previous
#include <cuda_runtime.h>
#include <math.h>

#define NCLS 19
#define BB   8
#define CC   512
#define HW   16384      // 128*128
#define GPB  4          // channels per block
#define THREADS_A 256   // 8 warps: tensor = w&1, local channel = w>>1

// Scratch (single-writer per slot -> deterministic, no float atomics)
__device__ float         g_partial[2][BB][NCLS][CC];  // [tensor][b][class][channel]
__device__ int           g_cnt_part[BB][NCLS];
__device__ float         g_norm[2][NCLS][CC];
__device__ unsigned int  g_lab8[BB][HW / 4];          // packed u8 labels, 4/word

// ---------------------------------------------------------------------------
// Kernel P: pack labels int32 -> u8 (4/word) and compute per-class counts.
// One block per image. ~0.6 MB traffic total.
// ---------------------------------------------------------------------------
__global__ void __launch_bounds__(256) kP(const int* __restrict__ lab) {
    __shared__ int cnt[32];
    const int b   = blockIdx.x;
    const int tid = threadIdx.x;
    if (tid < 32) cnt[tid] = 0;
    __syncthreads();

    const int4* lab4 = (const int4*)(lab + (size_t)b * HW);
    for (int i = tid; i < HW / 4; i += 256) {
        int4 v = lab4[i];
        g_lab8[b][i] = (unsigned int)v.x | ((unsigned int)v.y << 8) |
                       ((unsigned int)v.z << 16) | ((unsigned int)v.w << 24);
        atomicAdd(&cnt[v.x], 1);
        atomicAdd(&cnt[v.y], 1);
        atomicAdd(&cnt[v.z], 1);
        atomicAdd(&cnt[v.w], 1);
    }
    __syncthreads();
    if (tid < NCLS) g_cnt_part[b][tid] = cnt[tid];
}

// ---------------------------------------------------------------------------
// Kernel A: streaming segment-sum.
// Block (cg, b): channels [cg*4, cg*4+4) of image b, both tensors.
// Warp w: tensor = w&1, local channel = w>>1. Private accumulator slab
// acc[w][19][32]: bank == lane -> conflict-free, no cross-thread sharing.
// smem/block = 8*2432 = 19456 B -> 8 blocks/SM = 64 warps (full occupancy).
// Labels read as packed u8 words from global (L1/L2-hit, same stream for all
// warps of a block).
// ---------------------------------------------------------------------------
__global__ void __launch_bounds__(THREADS_A, 8) kA(const float* __restrict__ fs,
                                                   const float* __restrict__ ft) {
    extern __shared__ float acc[];                    // 8*19*32 floats = 19456 B

    const int tid  = threadIdx.x;
    const int lane = tid & 31;
    const int w    = tid >> 5;
    const int cg   = blockIdx.x;
    const int b    = blockIdx.y;

    for (int i = tid; i < 8 * NCLS * 32; i += THREADS_A) acc[i] = 0.0f;
    __syncthreads();

    const int tensor = w & 1;
    const int c      = cg * GPB + (w >> 1);           // w>>1 in 0..3
    const float4* f  = (const float4*)((tensor ? ft : fs) + ((size_t)b * CC + c) * HW);
    const unsigned int* __restrict__ labw = g_lab8[b];
    float* accw = acc + w * NCLS * 32;

    #pragma unroll 4
    for (int i = lane; i < HW / 4; i += 32) {
        unsigned int l = __ldg(labw + i);
        float4 v = f[i];
        accw[((l      ) & 0xFFu) * 32 + lane] += v.x;
        accw[((l >>  8) & 0xFFu) * 32 + lane] += v.y;
        accw[((l >> 16) & 0xFFu) * 32 + lane] += v.z;
        accw[((l >> 24)        ) * 32 + lane] += v.w;
    }
    __syncwarp();

    // flush: each warp reduces its own [19][32] slab
    for (int k = 0; k < NCLS; k++) {
        float v = accw[k * 32 + lane];
        #pragma unroll
        for (int o = 16; o; o >>= 1) v += __shfl_down_sync(0xFFFFFFFFu, v, o);
        if (lane == 0) g_partial[tensor][b][k][c] = v;
    }
}

// ---------------------------------------------------------------------------
// Kernel C1: mean + L2-normalize. Grid 38: block = (tensor s, class k).
// ---------------------------------------------------------------------------
__global__ void __launch_bounds__(128) kC1() {
    __shared__ float wss[4];
    __shared__ float sh_denom;
    const int t    = threadIdx.x;
    const int lane = t & 31;
    const int w    = t >> 5;
    const int task = blockIdx.x;
    const int s    = task >= NCLS ? 1 : 0;
    const int k    = task >= NCLS ? task - NCLS : task;

    if (t == 0) {
        int c = 0;
        #pragma unroll
        for (int b = 0; b < BB; b++) c += g_cnt_part[b][k];
        sh_denom = fmaxf((float)c, 1.0f);
    }
    __syncthreads();
    const float denom = sh_denom;

    float m[4];
    float ss = 0.0f;
    #pragma unroll
    for (int ch = 0; ch < 4; ch++) {
        const int c = ch * 128 + t;
        float sum = 0.0f;
        #pragma unroll
        for (int b = 0; b < BB; b++) sum += g_partial[s][b][k][c];
        float mean = sum / denom;
        m[ch] = mean;
        ss += mean * mean;
    }
    #pragma unroll
    for (int o = 16; o; o >>= 1) ss += __shfl_xor_sync(0xFFFFFFFFu, ss, o);
    if (lane == 0) wss[w] = ss;
    __syncthreads();
    const float tot = wss[0] + wss[1] + wss[2] + wss[3];
    const float inv = 1.0f / fmaxf(sqrtf(tot), 1e-12f);
    #pragma unroll
    for (int ch = 0; ch < 4; ch++)
        g_norm[s][k][ch * 128 + t] = m[ch] * inv;
}

// ---------------------------------------------------------------------------
// Kernel C2: logits (19x19 warp-dots), logsumexp, masked mean -> scalar.
// ---------------------------------------------------------------------------
__global__ void __launch_bounds__(640) kC2(float* __restrict__ out) {
    __shared__ float sh_log[NCLS][NCLS];
    __shared__ int   sh_cnt[NCLS];
    __shared__ float sh_pc[NCLS];
    const int tid  = threadIdx.x;
    const int w    = tid >> 5;
    const int lane = tid & 31;

    if (tid < NCLS) {
        int c = 0;
        #pragma unroll
        for (int b = 0; b < BB; b++) c += g_cnt_part[b][tid];
        sh_cnt[tid] = c;
    }

    if (w < NCLS) {                       // warp w -> logits row w
        const float* si = &g_norm[0][w][0];
        for (int j = 0; j < NCLS; j++) {
            const float* tj = &g_norm[1][j][0];
            float p = 0.0f;
            #pragma unroll
            for (int ch = 0; ch < CC / 32; ch++)
                p += si[ch * 32 + lane] * tj[ch * 32 + lane];
            #pragma unroll
            for (int o = 16; o; o >>= 1) p += __shfl_down_sync(0xFFFFFFFFu, p, o);
            if (lane == 0) sh_log[w][j] = p * 10.0f;   // / TEMP (0.1)
        }
    }
    __syncthreads();

    if (tid < NCLS) {
        float mx = -1e30f;
        for (int j = 0; j < NCLS; j++) mx = fmaxf(mx, sh_log[tid][j]);
        float s = 0.0f;
        for (int j = 0; j < NCLS; j++) s += expf(sh_log[tid][j] - mx);
        float lse = mx + logf(s);
        sh_pc[tid] = sh_log[tid][tid] - lse;
    }
    __syncthreads();

    if (tid == 0) {
        float sum = 0.0f;
        int np = 0;
        for (int k = 0; k < NCLS; k++)
            if (sh_cnt[k] > 0) { sum += sh_pc[k]; np++; }
        out[0] = -sum / (float)np;
    }
}

// ---------------------------------------------------------------------------
extern "C" void kernel_launch(void* const* d_in, const int* in_sizes, int n_in,
                              void* d_out, int out_size) {
    const float* fs  = (const float*)d_in[0];
    const float* ft  = (const float*)d_in[1];
    const int*   lab = (const int*)d_in[2];

    const size_t smemA = (size_t)8 * NCLS * 32 * 4;   // 19456 B
    cudaFuncSetAttribute(kA, cudaFuncAttributeMaxDynamicSharedMemorySize, (int)smemA);

    kP<<<BB, 256>>>(lab);
    kA<<<dim3(CC / GPB, BB), THREADS_A, smemA>>>(fs, ft);
    kC1<<<2 * NCLS, 128>>>();
    kC2<<<1, 640>>>((float*)d_out);
}

// round 7
// speedup vs baseline: 1.1273x; 1.0008x over previous
#include <cuda_runtime.h>
#include <math.h>

#define NCLS 19
#define BB   8
#define CC   512
#define HW   16384      // 128*128
#define THREADS_A 128   // 4 warps: tensor = w&1, quad = w>>1 (4 channels each)

// Scratch (single-writer per slot -> deterministic, no float atomics)
__device__ float         g_partial[2][BB][NCLS][CC];  // [tensor][b][class][channel]
__device__ int           g_cnt_part[BB][NCLS];
__device__ float         g_norm[2][NCLS][CC];
__device__ unsigned int  g_lab8[BB][HW / 4];          // packed u8 labels, 4/word

// ---------------------------------------------------------------------------
// Kernel P: pack labels int32 -> u8 (4/word) and compute per-class counts.
// ---------------------------------------------------------------------------
__global__ void __launch_bounds__(256) kP(const int* __restrict__ lab) {
    __shared__ int cnt[32];
    const int b   = blockIdx.x;
    const int tid = threadIdx.x;
    if (tid < 32) cnt[tid] = 0;
    __syncthreads();

    const int4* lab4 = (const int4*)(lab + (size_t)b * HW);
    for (int i = tid; i < HW / 4; i += 256) {
        int4 v = lab4[i];
        g_lab8[b][i] = (unsigned int)v.x | ((unsigned int)v.y << 8) |
                       ((unsigned int)v.z << 16) | ((unsigned int)v.w << 24);
        atomicAdd(&cnt[v.x], 1);
        atomicAdd(&cnt[v.y], 1);
        atomicAdd(&cnt[v.z], 1);
        atomicAdd(&cnt[v.w], 1);
    }
    __syncthreads();
    if (tid < NCLS) g_cnt_part[b][tid] = cnt[tid];
}

// ---------------------------------------------------------------------------
// Kernel A v2: streaming segment-sum, 4 channels/warp, float4 accumulators.
// Block (cg, b): channels [cg*8, cg*8+8), both tensors. Warp w: tensor=w&1,
// quad=w>>1 -> channels c0..c0+3. acc slot = float4 per (class, lane):
// .x...w = the 4 channels. Per 2048 B features: 4 LDG.128 + 4 LDS.128 +
// 4 STS.128 + 1 label LDG. Software-pipelined prefetch hides DRAM latency.
// smem = 4 warps * 19*32*16 B = 38912 B -> 5 blocks/SM.
// ---------------------------------------------------------------------------
__global__ void __launch_bounds__(THREADS_A, 5) kA(const float* __restrict__ fs,
                                                   const float* __restrict__ ft) {
    extern __shared__ float4 acc4[];                  // [4][19*32]

    const int tid  = threadIdx.x;
    const int lane = tid & 31;
    const int w    = tid >> 5;
    const int cg   = blockIdx.x;
    const int b    = blockIdx.y;

    for (int i = tid; i < 4 * NCLS * 32; i += THREADS_A)
        acc4[i] = make_float4(0.f, 0.f, 0.f, 0.f);
    __syncthreads();

    const int tensor = w & 1;
    const int c0     = cg * 8 + (w >> 1) * 4;         // 4 consecutive channels
    const float4* f  = (const float4*)((tensor ? ft : fs) + ((size_t)b * CC + c0) * HW);
    const unsigned int* __restrict__ labw = g_lab8[b];
    float4* accw = acc4 + w * NCLS * 32;

    // software pipeline: prefetch group i+32 while consuming group i
    int i = lane;
    unsigned int l = __ldg(labw + i);
    float4 va = f[i], vb = f[i + 4096], vc = f[i + 8192], vd = f[i + 12288];

    for (int ii = lane + 32; ii < HW / 4; ii += 32) {
        unsigned int nl = __ldg(labw + ii);
        float4 na = f[ii], nb = f[ii + 4096], nc = f[ii + 8192], nd = f[ii + 12288];

        #pragma unroll
        for (int j = 0; j < 4; j++) {
            const int k = (l >> (8 * j)) & 0xFF;
            float4* slot = &accw[k * 32 + lane];
            float4 cur = *slot;
            cur.x += (j == 0 ? va.x : j == 1 ? va.y : j == 2 ? va.z : va.w);
            cur.y += (j == 0 ? vb.x : j == 1 ? vb.y : j == 2 ? vb.z : vb.w);
            cur.z += (j == 0 ? vc.x : j == 1 ? vc.y : j == 2 ? vc.z : vc.w);
            cur.w += (j == 0 ? vd.x : j == 1 ? vd.y : j == 2 ? vd.z : vd.w);
            *slot = cur;
        }
        l = nl; va = na; vb = nb; vc = nc; vd = nd;
    }
    #pragma unroll
    for (int j = 0; j < 4; j++) {
        const int k = (l >> (8 * j)) & 0xFF;
        float4* slot = &accw[k * 32 + lane];
        float4 cur = *slot;
        cur.x += (j == 0 ? va.x : j == 1 ? va.y : j == 2 ? va.z : va.w);
        cur.y += (j == 0 ? vb.x : j == 1 ? vb.y : j == 2 ? vb.z : vb.w);
        cur.z += (j == 0 ? vc.x : j == 1 ? vc.y : j == 2 ? vc.z : vc.w);
        cur.w += (j == 0 ? vd.x : j == 1 ? vd.y : j == 2 ? vd.z : vd.w);
        *slot = cur;
    }
    __syncwarp();

    // flush: reduce each (class, 4-channel) float4 across 32 lanes
    for (int k = 0; k < NCLS; k++) {
        float4 v = accw[k * 32 + lane];
        #pragma unroll
        for (int o = 16; o; o >>= 1) {
            v.x += __shfl_down_sync(0xFFFFFFFFu, v.x, o);
            v.y += __shfl_down_sync(0xFFFFFFFFu, v.y, o);
            v.z += __shfl_down_sync(0xFFFFFFFFu, v.z, o);
            v.w += __shfl_down_sync(0xFFFFFFFFu, v.w, o);
        }
        if (lane == 0)
            *(float4*)&g_partial[tensor][b][k][c0] = v;
    }
}

// ---------------------------------------------------------------------------
// Kernel C1: mean + L2-normalize. Grid 38: block = (tensor s, class k).
// ---------------------------------------------------------------------------
__global__ void __launch_bounds__(128) kC1() {
    __shared__ float wss[4];
    __shared__ float sh_denom;
    const int t    = threadIdx.x;
    const int lane = t & 31;
    const int w    = t >> 5;
    const int task = blockIdx.x;
    const int s    = task >= NCLS ? 1 : 0;
    const int k    = task >= NCLS ? task - NCLS : task;

    if (t == 0) {
        int c = 0;
        #pragma unroll
        for (int b = 0; b < BB; b++) c += g_cnt_part[b][k];
        sh_denom = fmaxf((float)c, 1.0f);
    }
    __syncthreads();
    const float denom = sh_denom;

    float m[4];
    float ss = 0.0f;
    #pragma unroll
    for (int ch = 0; ch < 4; ch++) {
        const int c = ch * 128 + t;
        float sum = 0.0f;
        #pragma unroll
        for (int b = 0; b < BB; b++) sum += g_partial[s][b][k][c];
        float mean = sum / denom;
        m[ch] = mean;
        ss += mean * mean;
    }
    #pragma unroll
    for (int o = 16; o; o >>= 1) ss += __shfl_xor_sync(0xFFFFFFFFu, ss, o);
    if (lane == 0) wss[w] = ss;
    __syncthreads();
    const float tot = wss[0] + wss[1] + wss[2] + wss[3];
    const float inv = 1.0f / fmaxf(sqrtf(tot), 1e-12f);
    #pragma unroll
    for (int ch = 0; ch < 4; ch++)
        g_norm[s][k][ch * 128 + t] = m[ch] * inv;
}

// ---------------------------------------------------------------------------
// Kernel C2 v2: stage g_norm in smem, then logits + logsumexp + loss.
// 640 threads. smem 77824 B (dynamic). si row hoisted to registers.
// ---------------------------------------------------------------------------
__global__ void __launch_bounds__(640) kC2(float* __restrict__ out) {
    extern __shared__ float nrm[];        // [2][NCLS][CC] = 19456 floats
    __shared__ float sh_log[NCLS][NCLS];
    __shared__ int   sh_cnt[NCLS];
    __shared__ float sh_pc[NCLS];
    const int tid  = threadIdx.x;
    const int w    = tid >> 5;
    const int lane = tid & 31;

    // coalesced stage of both normalized matrices
    const float4* src = (const float4*)&g_norm[0][0][0];
    float4*       dst = (float4*)nrm;
    for (int i = tid; i < 2 * NCLS * CC / 4; i += 640) dst[i] = src[i];

    if (tid < NCLS) {
        int c = 0;
        #pragma unroll
        for (int b = 0; b < BB; b++) c += g_cnt_part[b][tid];
        sh_cnt[tid] = c;
    }
    __syncthreads();

    if (w < NCLS) {                       // warp w -> logits row w
        const float* si = &nrm[(size_t)w * CC];            // tensor 0, class w
        float sreg[CC / 32];
        #pragma unroll
        for (int ch = 0; ch < CC / 32; ch++) sreg[ch] = si[ch * 32 + lane];

        for (int j = 0; j < NCLS; j++) {
            const float* tj = &nrm[(size_t)(NCLS + j) * CC];  // tensor 1, class j
            float p = 0.0f;
            #pragma unroll
            for (int ch = 0; ch < CC / 32; ch++)
                p += sreg[ch] * tj[ch * 32 + lane];
            #pragma unroll
            for (int o = 16; o; o >>= 1) p += __shfl_down_sync(0xFFFFFFFFu, p, o);
            if (lane == 0) sh_log[w][j] = p * 10.0f;   // / TEMP (0.1)
        }
    }
    __syncthreads();

    if (tid < NCLS) {
        float mx = -1e30f;
        for (int j = 0; j < NCLS; j++) mx = fmaxf(mx, sh_log[tid][j]);
        float s = 0.0f;
        for (int j = 0; j < NCLS; j++) s += expf(sh_log[tid][j] - mx);
        float lse = mx + logf(s);
        sh_pc[tid] = sh_log[tid][tid] - lse;
    }
    __syncthreads();

    if (tid == 0) {
        float sum = 0.0f;
        int np = 0;
        for (int k = 0; k < NCLS; k++)
            if (sh_cnt[k] > 0) { sum += sh_pc[k]; np++; }
        out[0] = -sum / (float)np;
    }
}

// ---------------------------------------------------------------------------
extern "C" void kernel_launch(void* const* d_in, const int* in_sizes, int n_in,
                              void* d_out, int out_size) {
    const float* fs  = (const float*)d_in[0];
    const float* ft  = (const float*)d_in[1];
    const int*   lab = (const int*)d_in[2];

    const size_t smemA  = (size_t)4 * NCLS * 32 * 16;      // 38912 B
    const size_t smemC2 = (size_t)2 * NCLS * CC * 4;       // 77824 B
    cudaFuncSetAttribute(kA,  cudaFuncAttributeMaxDynamicSharedMemorySize, (int)smemA);
    cudaFuncSetAttribute(kC2, cudaFuncAttributeMaxDynamicSharedMemorySize, (int)smemC2);

    kP<<<BB, 256>>>(lab);
    kA<<<dim3(CC / 8, BB), THREADS_A, smemA>>>(fs, ft);
    kC1<<<2 * NCLS, 128>>>();
    kC2<<<1, 640, smemC2>>>((float*)d_out);
}

// round 8
// speedup vs baseline: 1.2064x; 1.0702x over previous
#include <cuda_runtime.h>
#include <math.h>

#define NCLS 19
#define BB   8
#define CC   512
#define HW   16384      // 128*128
#define GPB  4          // channels per block
#define THREADS_A 256   // 8 warps: tensor = w&1, local channel = w>>1

// Scratch (single-writer per slot -> deterministic, no float atomics)
__device__ float         g_partial[2][BB][NCLS][CC];  // [tensor][b][class][channel]
__device__ int           g_cnt_part[BB][NCLS];
__device__ float         g_norm[2][NCLS][CC];
__device__ unsigned int  g_lab8[BB][HW / 4];          // packed u8 labels, 4/word

// ---------------------------------------------------------------------------
// Kernel P: pack labels int32 -> u8 (4/word) and compute per-class counts.
// ---------------------------------------------------------------------------
__global__ void __launch_bounds__(256) kP(const int* __restrict__ lab) {
    __shared__ int cnt[32];
    const int b   = blockIdx.x;
    const int tid = threadIdx.x;
    if (tid < 32) cnt[tid] = 0;
    __syncthreads();

    const int4* lab4 = (const int4*)(lab + (size_t)b * HW);
    for (int i = tid; i < HW / 4; i += 256) {
        int4 v = lab4[i];
        g_lab8[b][i] = (unsigned int)v.x | ((unsigned int)v.y << 8) |
                       ((unsigned int)v.z << 16) | ((unsigned int)v.w << 24);
        atomicAdd(&cnt[v.x], 1);
        atomicAdd(&cnt[v.y], 1);
        atomicAdd(&cnt[v.z], 1);
        atomicAdd(&cnt[v.w], 1);
    }
    __syncthreads();
    if (tid < NCLS) g_cnt_part[b][tid] = cnt[tid];
}

// ---------------------------------------------------------------------------
// Kernel A (R6 layout — measured fastest): streaming segment-sum.
// Block (cg, b): channels [cg*4, cg*4+4) of image b, both tensors.
// Warp w: tensor = w&1, local channel = w>>1. Private accumulator slab
// acc[w][19][32], scalar floats: bank == lane -> conflict-free LDS/STS.
// smem/block = 8*2432 = 19456 B -> 8 blocks/SM = 64 warps (full occupancy).
// ---------------------------------------------------------------------------
__global__ void __launch_bounds__(THREADS_A, 8) kA(const float* __restrict__ fs,
                                                   const float* __restrict__ ft) {
    extern __shared__ float acc[];                    // 8*19*32 floats = 19456 B

    const int tid  = threadIdx.x;
    const int lane = tid & 31;
    const int w    = tid >> 5;
    const int cg   = blockIdx.x;
    const int b    = blockIdx.y;

    for (int i = tid; i < 8 * NCLS * 32; i += THREADS_A) acc[i] = 0.0f;
    __syncthreads();

    const int tensor = w & 1;
    const int c      = cg * GPB + (w >> 1);           // w>>1 in 0..3
    const float4* f  = (const float4*)((tensor ? ft : fs) + ((size_t)b * CC + c) * HW);
    const unsigned int* __restrict__ labw = g_lab8[b];
    float* accw = acc + w * NCLS * 32;

    #pragma unroll 4
    for (int i = lane; i < HW / 4; i += 32) {
        unsigned int l = __ldg(labw + i);
        float4 v = f[i];
        accw[((l      ) & 0xFFu) * 32 + lane] += v.x;
        accw[((l >>  8) & 0xFFu) * 32 + lane] += v.y;
        accw[((l >> 16) & 0xFFu) * 32 + lane] += v.z;
        accw[((l >> 24)        ) * 32 + lane] += v.w;
    }
    __syncwarp();

    // flush: each warp reduces its own [19][32] slab
    for (int k = 0; k < NCLS; k++) {
        float v = accw[k * 32 + lane];
        #pragma unroll
        for (int o = 16; o; o >>= 1) v += __shfl_down_sync(0xFFFFFFFFu, v, o);
        if (lane == 0) g_partial[tensor][b][k][c] = v;
    }
}

// ---------------------------------------------------------------------------
// Kernel C1: mean + L2-normalize. Grid 38: block = (tensor s, class k).
// ---------------------------------------------------------------------------
__global__ void __launch_bounds__(128) kC1() {
    __shared__ float wss[4];
    __shared__ float sh_denom;
    const int t    = threadIdx.x;
    const int lane = t & 31;
    const int w    = t >> 5;
    const int task = blockIdx.x;
    const int s    = task >= NCLS ? 1 : 0;
    const int k    = task >= NCLS ? task - NCLS : task;

    if (t == 0) {
        int c = 0;
        #pragma unroll
        for (int b = 0; b < BB; b++) c += g_cnt_part[b][k];
        sh_denom = fmaxf((float)c, 1.0f);
    }
    __syncthreads();
    const float denom = sh_denom;

    float m[4];
    float ss = 0.0f;
    #pragma unroll
    for (int ch = 0; ch < 4; ch++) {
        const int c = ch * 128 + t;
        float sum = 0.0f;
        #pragma unroll
        for (int b = 0; b < BB; b++) sum += g_partial[s][b][k][c];
        float mean = sum / denom;
        m[ch] = mean;
        ss += mean * mean;
    }
    #pragma unroll
    for (int o = 16; o; o >>= 1) ss += __shfl_xor_sync(0xFFFFFFFFu, ss, o);
    if (lane == 0) wss[w] = ss;
    __syncthreads();
    const float tot = wss[0] + wss[1] + wss[2] + wss[3];
    const float inv = 1.0f / fmaxf(sqrtf(tot), 1e-12f);
    #pragma unroll
    for (int ch = 0; ch < 4; ch++)
        g_norm[s][k][ch * 128 + t] = m[ch] * inv;
}

// ---------------------------------------------------------------------------
// Kernel C2: stage g_norm in smem, then logits + logsumexp + loss.
// 640 threads. smem 77824 B (dynamic). si row hoisted to registers.
// ---------------------------------------------------------------------------
__global__ void __launch_bounds__(640) kC2(float* __restrict__ out) {
    extern __shared__ float nrm[];        // [2][NCLS][CC] = 19456 floats
    __shared__ float sh_log[NCLS][NCLS];
    __shared__ int   sh_cnt[NCLS];
    __shared__ float sh_pc[NCLS];
    const int tid  = threadIdx.x;
    const int w    = tid >> 5;
    const int lane = tid & 31;

    // coalesced stage of both normalized matrices
    const float4* src = (const float4*)&g_norm[0][0][0];
    float4*       dst = (float4*)nrm;
    for (int i = tid; i < 2 * NCLS * CC / 4; i += 640) dst[i] = src[i];

    if (tid < NCLS) {
        int c = 0;
        #pragma unroll
        for (int b = 0; b < BB; b++) c += g_cnt_part[b][tid];
        sh_cnt[tid] = c;
    }
    __syncthreads();

    if (w < NCLS) {                       // warp w -> logits row w
        const float* si = &nrm[(size_t)w * CC];            // tensor 0, class w
        float sreg[CC / 32];
        #pragma unroll
        for (int ch = 0; ch < CC / 32; ch++) sreg[ch] = si[ch * 32 + lane];

        for (int j = 0; j < NCLS; j++) {
            const float* tj = &nrm[(size_t)(NCLS + j) * CC];  // tensor 1, class j
            float p = 0.0f;
            #pragma unroll
            for (int ch = 0; ch < CC / 32; ch++)
                p += sreg[ch] * tj[ch * 32 + lane];
            #pragma unroll
            for (int o = 16; o; o >>= 1) p += __shfl_down_sync(0xFFFFFFFFu, p, o);
            if (lane == 0) sh_log[w][j] = p * 10.0f;   // / TEMP (0.1)
        }
    }
    __syncthreads();

    if (tid < NCLS) {
        float mx = -1e30f;
        for (int j = 0; j < NCLS; j++) mx = fmaxf(mx, sh_log[tid][j]);
        float s = 0.0f;
        for (int j = 0; j < NCLS; j++) s += expf(sh_log[tid][j] - mx);
        float lse = mx + logf(s);
        sh_pc[tid] = sh_log[tid][tid] - lse;
    }
    __syncthreads();

    if (tid == 0) {
        float sum = 0.0f;
        int np = 0;
        for (int k = 0; k < NCLS; k++)
            if (sh_cnt[k] > 0) { sum += sh_pc[k]; np++; }
        out[0] = -sum / (float)np;
    }
}

// ---------------------------------------------------------------------------
extern "C" void kernel_launch(void* const* d_in, const int* in_sizes, int n_in,
                              void* d_out, int out_size) {
    const float* fs  = (const float*)d_in[0];
    const float* ft  = (const float*)d_in[1];
    const int*   lab = (const int*)d_in[2];

    const size_t smemA  = (size_t)8 * NCLS * 32 * 4;       // 19456 B
    const size_t smemC2 = (size_t)2 * NCLS * CC * 4;       // 77824 B
    cudaFuncSetAttribute(kA,  cudaFuncAttributeMaxDynamicSharedMemorySize, (int)smemA);
    cudaFuncSetAttribute(kC2, cudaFuncAttributeMaxDynamicSharedMemorySize, (int)smemC2);

    kP<<<BB, 256>>>(lab);
    kA<<<dim3(CC / GPB, BB), THREADS_A, smemA>>>(fs, ft);
    kC1<<<2 * NCLS, 128>>>();
    kC2<<<1, 640, smemC2>>>((float*)d_out);
}